// round 12
// baseline (speedup 1.0000x reference)
#include <cuda_runtime.h>
#include <math.h>
#include <stdint.h>

#define BB 128
#define TT 256
#define DD 512
#define HH 256
#define NC 96
#define BT (BB*TT)

// ---------------- scratch (static device globals; no runtime alloc) --------
__device__ float g_xg1f[(size_t)BT*1024];
__device__ float g_xg1b[(size_t)BT*1024];
__device__ float g_xg2f[(size_t)BT*1024];
__device__ float g_xg2b[(size_t)BT*1024];
__device__ float g_h1f[(size_t)BT*HH];
__device__ float g_h1b[(size_t)BT*HH];
__device__ float g_hcat[(size_t)BT*2*HH];
__device__ float g_xgFf[(size_t)BT*384];
__device__ float g_xgBf[(size_t)BT*384];
__device__ float g_potB[(size_t)BT*NC];

// ---------------------------------------------------------------------------
// GEMM v2 (unchanged): 128x128 tile, BK=16, f32x2, reg double-buffer.
// ---------------------------------------------------------------------------
__global__ __launch_bounds__(256, 2)
void gemm_bias_kernel(const float* __restrict__ A, const float* __restrict__ Bm,
                      const float* __restrict__ bias, float* __restrict__ C,
                      int M, int N, int K)
{
    __shared__ float As[16][132];
    __shared__ float Bs[16][128];

    const int tid = threadIdx.x;
    const int m0  = blockIdx.y * 128;
    const int n0  = blockIdx.x * 128;
    const int txn = tid & 15;
    const int tym = tid >> 4;

    const int arow = tid >> 2;
    const int akg  = (tid & 3) * 4;
    const int bkk = tid >> 5;
    const int bn  = (tid & 31) * 4;

    unsigned long long acc[4][8];
#pragma unroll
    for (int p = 0; p < 4; p++)
#pragma unroll
        for (int j = 0; j < 8; j++) acc[p][j] = 0ull;

    const int T = K / 16;
    float4 aR0, aR1, bR0, bR1;

    aR0 = *(const float4*)&A[(size_t)(m0 + arow) * K + akg];
    aR1 = *(const float4*)&A[(size_t)(m0 + 64 + arow) * K + akg];
    bR0 = *(const float4*)&Bm[(size_t)bkk * N + n0 + bn];
    bR1 = *(const float4*)&Bm[(size_t)(8 + bkk) * N + n0 + bn];
    {
        As[akg + 0][arow] = aR0.x; As[akg + 1][arow] = aR0.y;
        As[akg + 2][arow] = aR0.z; As[akg + 3][arow] = aR0.w;
        As[akg + 0][64 + arow] = aR1.x; As[akg + 1][64 + arow] = aR1.y;
        As[akg + 2][64 + arow] = aR1.z; As[akg + 3][64 + arow] = aR1.w;
        *(float4*)&Bs[bkk][bn] = bR0;
        *(float4*)&Bs[8 + bkk][bn] = bR1;
    }
    __syncthreads();

    for (int t = 0; t < T; t++) {
        if (t + 1 < T) {
            int k0 = (t + 1) * 16;
            aR0 = *(const float4*)&A[(size_t)(m0 + arow) * K + k0 + akg];
            aR1 = *(const float4*)&A[(size_t)(m0 + 64 + arow) * K + k0 + akg];
            bR0 = *(const float4*)&Bm[(size_t)(k0 + bkk) * N + n0 + bn];
            bR1 = *(const float4*)&Bm[(size_t)(k0 + 8 + bkk) * N + n0 + bn];
        }
#pragma unroll
        for (int kk = 0; kk < 16; kk++) {
            ulonglong2 aP0 = *(const ulonglong2*)&As[kk][tym * 8];
            ulonglong2 aP1 = *(const ulonglong2*)&As[kk][tym * 8 + 4];
            float4 b0 = *(const float4*)&Bs[kk][txn * 8];
            float4 b1 = *(const float4*)&Bs[kk][txn * 8 + 4];
            unsigned long long bd[8];
            asm("mov.b64 %0, {%1, %1};" : "=l"(bd[0]) : "f"(b0.x));
            asm("mov.b64 %0, {%1, %1};" : "=l"(bd[1]) : "f"(b0.y));
            asm("mov.b64 %0, {%1, %1};" : "=l"(bd[2]) : "f"(b0.z));
            asm("mov.b64 %0, {%1, %1};" : "=l"(bd[3]) : "f"(b0.w));
            asm("mov.b64 %0, {%1, %1};" : "=l"(bd[4]) : "f"(b1.x));
            asm("mov.b64 %0, {%1, %1};" : "=l"(bd[5]) : "f"(b1.y));
            asm("mov.b64 %0, {%1, %1};" : "=l"(bd[6]) : "f"(b1.z));
            asm("mov.b64 %0, {%1, %1};" : "=l"(bd[7]) : "f"(b1.w));
            unsigned long long ap[4] = {aP0.x, aP0.y, aP1.x, aP1.y};
#pragma unroll
            for (int p = 0; p < 4; p++)
#pragma unroll
                for (int j = 0; j < 8; j++)
                    asm("fma.rn.f32x2 %0, %1, %2, %0;"
                        : "+l"(acc[p][j]) : "l"(ap[p]), "l"(bd[j]));
        }
        __syncthreads();
        if (t + 1 < T) {
            As[akg + 0][arow] = aR0.x; As[akg + 1][arow] = aR0.y;
            As[akg + 2][arow] = aR0.z; As[akg + 3][arow] = aR0.w;
            As[akg + 0][64 + arow] = aR1.x; As[akg + 1][64 + arow] = aR1.y;
            As[akg + 2][64 + arow] = aR1.z; As[akg + 3][64 + arow] = aR1.w;
            *(float4*)&Bs[bkk][bn] = bR0;
            *(float4*)&Bs[8 + bkk][bn] = bR1;
            __syncthreads();
        }
    }

    float4 z0 = *(const float4*)&bias[n0 + txn * 8];
    float4 z1 = *(const float4*)&bias[n0 + txn * 8 + 4];
    float bz[8] = {z0.x, z0.y, z0.z, z0.w, z1.x, z1.y, z1.z, z1.w};
#pragma unroll
    for (int p = 0; p < 4; p++) {
        float lo[8], hi[8];
#pragma unroll
        for (int j = 0; j < 8; j++)
            asm("mov.b64 {%0, %1}, %2;" : "=f"(lo[j]), "=f"(hi[j]) : "l"(acc[p][j]));
        size_t r0 = (size_t)(m0 + tym * 8 + 2 * p) * N + n0 + txn * 8;
        size_t r1 = r0 + N;
        float4 v;
        v.x = lo[0] + bz[0]; v.y = lo[1] + bz[1]; v.z = lo[2] + bz[2]; v.w = lo[3] + bz[3];
        *(float4*)&C[r0] = v;
        v.x = lo[4] + bz[4]; v.y = lo[5] + bz[5]; v.z = lo[6] + bz[6]; v.w = lo[7] + bz[7];
        *(float4*)&C[r0 + 4] = v;
        v.x = hi[0] + bz[0]; v.y = hi[1] + bz[1]; v.z = hi[2] + bz[2]; v.w = hi[3] + bz[3];
        *(float4*)&C[r1] = v;
        v.x = hi[4] + bz[4]; v.y = hi[5] + bz[5]; v.z = hi[6] + bz[6]; v.w = hi[7] + bz[7];
        *(float4*)&C[r1 + 4] = v;
    }
}

// ---------------------------------------------------------------------------
// Persistent dual-direction LSTM scan v4: R10 shape (256 thr) + cluster(8,1,1)
// DSMEM h-exchange. The 8 CTAs sharing (b0, dir) are one cluster; each gate
// thread PUSHES its h values into all 8 CTAs' hT (next buffer) via
// mapa + st.shared::cluster; step sync = barrier.cluster (release/acquire).
// No global h state, no atomics, no L2 round-trip on the critical path.
// ---------------------------------------------------------------------------
#define ZROW 33  // u64 per column row: 8 bpairs x 4 bands + 1 pad
#define SCAN_SMEM ((256*128 + 2*256*16) * 4 + 128*ZROW*8)

__global__ __launch_bounds__(256, 1) __cluster_dims__(8, 1, 1)
void scan_persist_kernel(const float* __restrict__ xgF, const float* __restrict__ xgB,
                         const float* __restrict__ WhF, const float* __restrict__ WhB,
                         float* __restrict__ outF, float* __restrict__ outB,
                         int outStride, int offF, int offB)
{
    extern __shared__ float sm[];
    float* Ws  = sm;                              // [256 k][128 c]
    float* hT0 = Ws + 256 * 128;                  // [256 k][16 b] buffer 0
    float* hT1 = hT0 + 256 * 16;                  // buffer 1
    unsigned long long* zP =
        (unsigned long long*)(hT1 + 256 * 16);    // [128 c][ZROW]

    const int tid = threadIdx.x;
    const int u0  = blockIdx.x * 32;
    const int b0  = blockIdx.y * 16;
    const int dir = blockIdx.z;
    const float* Wh = dir ? WhB : WhF;
    const float* xg = dir ? xgB : xgF;
    float* out = dir ? outB : outF;
    const int off = dir ? offB : offF;

    // stage Wh slice once: Ws[k][g*32+q] = Wh[k][g*256+u0+q]
#pragma unroll
    for (int i = 0; i < 32; i++) {
        int v = i * 256 + tid;
        int k = v >> 5, c4v = v & 31;
        int gate = c4v >> 3, q = c4v & 7;
        float4 w = *(const float4*)(Wh + (size_t)k * 1024 + gate * 256 + u0 + q * 4);
        *(float4*)(Ws + k * 128 + gate * 32 + q * 4) = w;
    }
    // zero hT0 (initial h = 0)
    for (int i = tid; i < 256 * 16; i += 256) hT0[i] = 0.0f;

    // z-phase mapping (R10): 32 colg(4c) x 2 bgz(8b) x 4 bands(64k)
    const int colg = tid & 31;
    const int bgz  = (tid >> 5) & 1;
    const int band = tid >> 6;
    const int c4   = colg * 4;

    // gate-phase mapping (R10): unit pairs
    const int gq = tid & 15;            // unit pair: u0 + gq*2, +1
    const int gb = tid >> 4;            // batch 0..15
    const int bg = b0 + gb;

    // precompute remote DSMEM addresses for this thread's h cell (j=0; j=1 adds 64B)
    uint32_t smem_u32;
    asm("{ .reg .u64 t; cvta.to.shared.u64 t, %1; cvt.u32.u64 %0, t; }"
        : "=r"(smem_u32) : "l"(sm));
    const uint32_t hb0 = smem_u32 + 256 * 128 * 4;
    const uint32_t hb1 = hb0 + 256 * 16 * 4;
    const uint32_t cellOff = (uint32_t)(((u0 + gq * 2) * 16 + gb) * 4);
    uint32_t ra0[8], ra1[8];
#pragma unroll
    for (int r = 0; r < 8; r++) {
        asm("mapa.shared::cluster.u32 %0, %1, %2;"
            : "=r"(ra0[r]) : "r"(hb0 + cellOff), "r"(r));
        asm("mapa.shared::cluster.u32 %0, %1, %2;"
            : "=r"(ra1[r]) : "r"(hb1 + cellOff), "r"(r));
    }

    float creg0 = 0.0f, creg1 = 0.0f;
    __syncthreads();   // hT0 zero + Ws visible locally

#pragma unroll 1
    for (int s = 0; s < TT; s++) {
        const int t = dir ? (TT - 1 - s) : s;
        const float* hTr = (s & 1) ? hT1 : hT0;

        // prefetch xg gate inputs (float2 per gate)
        const size_t xrow = ((size_t)bg * TT + t) * 1024;
        float2 xv[4];
#pragma unroll
        for (int g = 0; g < 4; g++)
            xv[g] = *(const float2*)(xg + xrow + g * 256 + u0 + gq * 2);

        // z partial: 4 cols x 4 b-pairs over this thread's 64-k band
        unsigned long long acc[4][4];
#pragma unroll
        for (int j = 0; j < 4; j++)
#pragma unroll
            for (int p = 0; p < 4; p++) acc[j][p] = 0ull;

        const float* hb = hTr + bgz * 8;
        const float* wb = Ws + c4;
        const int kb = band * 64;
#pragma unroll 4
        for (int kk = 0; kk < 64; kk++) {
            int k = kb + kk;
            ulonglong2 h01 = *(const ulonglong2*)(hb + k * 16);
            ulonglong2 h23 = *(const ulonglong2*)(hb + k * 16 + 4);
            float4 w4 = *(const float4*)(wb + k * 128);
            unsigned long long wd[4];
            asm("mov.b64 %0, {%1, %1};" : "=l"(wd[0]) : "f"(w4.x));
            asm("mov.b64 %0, {%1, %1};" : "=l"(wd[1]) : "f"(w4.y));
            asm("mov.b64 %0, {%1, %1};" : "=l"(wd[2]) : "f"(w4.z));
            asm("mov.b64 %0, {%1, %1};" : "=l"(wd[3]) : "f"(w4.w));
#pragma unroll
            for (int j = 0; j < 4; j++) {
                asm("fma.rn.f32x2 %0, %1, %2, %0;" : "+l"(acc[j][0]) : "l"(h01.x), "l"(wd[j]));
                asm("fma.rn.f32x2 %0, %1, %2, %0;" : "+l"(acc[j][1]) : "l"(h01.y), "l"(wd[j]));
                asm("fma.rn.f32x2 %0, %1, %2, %0;" : "+l"(acc[j][2]) : "l"(h23.x), "l"(wd[j]));
                asm("fma.rn.f32x2 %0, %1, %2, %0;" : "+l"(acc[j][3]) : "l"(h23.y), "l"(wd[j]));
            }
        }
#pragma unroll
        for (int j = 0; j < 4; j++)
#pragma unroll
            for (int p = 0; p < 4; p++)
                zP[(c4 + j) * ZROW + (bgz * 4 + p) * 4 + band] = acc[j][p];
        __syncthreads();

        // gate phase: thread handles units u0+gq*2, +1 for batch gb
        {
            const unsigned* zw = (const unsigned*)zP;
            const int bp4 = (gb >> 1) * 4;
            const int lohi = gb & 1;
            const uint32_t* rr = (s & 1) ? ra0 : ra1;   // write hT[(s+1)&1]
            float hn2[2];
#pragma unroll
            for (int j = 0; j < 2; j++) {
                float zz[4];
#pragma unroll
                for (int g = 0; g < 4; g++) {
                    int c = g * 32 + gq * 2 + j;
                    const unsigned* r = zw + 2 * (c * ZROW + bp4) + lohi;
                    zz[g] = __uint_as_float(r[0]) + __uint_as_float(r[2])
                          + __uint_as_float(r[4]) + __uint_as_float(r[6]);
                }
                float zi = zz[0] + (j ? xv[0].y : xv[0].x);
                float zf = zz[1] + (j ? xv[1].y : xv[1].x);
                float zg = zz[2] + (j ? xv[2].y : xv[2].x);
                float zo = zz[3] + (j ? xv[3].y : xv[3].x);
                float iv = 1.f / (1.f + expf(-zi));
                float fv = 1.f / (1.f + expf(-zf));
                float ov = 1.f / (1.f + expf(-zo));
                float cold = j ? creg1 : creg0;
                float cn = fv * cold + iv * tanhf(zg);
                float hn = ov * tanhf(cn);
                if (j) creg1 = cn; else creg0 = cn;
                hn2[j] = hn;
                // push h to all 8 cluster CTAs' next-step hT
#pragma unroll
                for (int r = 0; r < 8; r++)
                    asm volatile("st.shared::cluster.f32 [%0], %1;"
                                 :: "r"(rr[r] + j * 64), "f"(hn) : "memory");
            }
            float2 o2; o2.x = hn2[0]; o2.y = hn2[1];
            *(float2*)(out + ((size_t)bg * TT + t) * outStride + off + u0 + gq * 2) = o2;
        }

        // cluster barrier: release our DSMEM pushes, acquire peers'
        asm volatile("barrier.cluster.arrive.aligned;" ::: "memory");
        asm volatile("barrier.cluster.wait.aligned;" ::: "memory");
    }
}

// ---------------------------------------------------------------------------
// Final LSTMs (C=96, softmax activation), one CTA per (sample, direction).
// ---------------------------------------------------------------------------
__device__ __forceinline__ float blockReduce96(float v, bool isMax,
                                               volatile float* red, int tid)
{
#pragma unroll
    for (int o = 16; o > 0; o >>= 1) {
        float w = __shfl_down_sync(0xffffffffu, v, o);
        v = isMax ? fmaxf(v, w) : v + w;
    }
    if (tid < 96 && (tid & 31) == 0) red[tid >> 5] = v;
    __syncthreads();
    float r = isMax ? fmaxf(fmaxf(red[0], red[1]), red[2])
                    : red[0] + red[1] + red[2];
    __syncthreads();
    return r;
}

#define FIN_SMEM ((96*384 + 384 + 96 + 96 + 4) * 4)

__global__ __launch_bounds__(384)
void final_lstm_kernel(const float* __restrict__ xgF, const float* __restrict__ xgB,
                       const float* __restrict__ WhF, const float* __restrict__ WhB,
                       float* __restrict__ potF, float* __restrict__ potB)
{
    extern __shared__ float sm[];
    float* WhS = sm;
    float* zS  = WhS + 96 * 384;
    float* hS  = zS + 384;
    float* cS  = hS + 96;
    float* red = cS + 96;
    const int tid = threadIdx.x;
    const int b = blockIdx.x;
    const int dir = blockIdx.y;

    const float* Wh = dir ? WhB : WhF;
    const float* xg = dir ? xgB : xgF;
    float* pot = dir ? potB : potF;

    for (int i = tid; i < 96 * 384; i += 384) WhS[i] = Wh[i];
    if (tid < 96) { hS[tid] = 0.f; cS[tid] = 0.f; }
    __syncthreads();

    for (int s = 0; s < TT; s++) {
        int t = dir ? (TT - 1 - s) : s;
        float a = xg[((size_t)b * TT + t) * 384 + tid];
#pragma unroll 4
        for (int k = 0; k < 96; k++) a += hS[k] * WhS[k * 384 + tid];
        zS[tid] = a;
        __syncthreads();

        bool v = tid < 96;
        float gv = v ? zS[192 + tid] : -1e30f;
        float gmax = blockReduce96(gv, true, red, tid);
        float ge = v ? expf(gv - gmax) : 0.f;
        float gsum = blockReduce96(ge, false, red, tid);
        float cn = 0.f;
        if (v) {
            float iv = 1.f / (1.f + expf(-zS[tid]));
            float fv = 1.f / (1.f + expf(-zS[96 + tid]));
            cn = fv * cS[tid] + iv * (ge / gsum);
        }
        float cmax = blockReduce96(v ? cn : -1e30f, true, red, tid);
        float ce = v ? expf(cn - cmax) : 0.f;
        float csum = blockReduce96(ce, false, red, tid);
        if (v) {
            float ov = 1.f / (1.f + expf(-zS[288 + tid]));
            float hv = ov * (ce / csum);
            cS[tid] = cn;
            hS[tid] = hv;
            pot[((size_t)b * TT + t) * 96 + tid] = hv;
        }
        __syncthreads();
    }
}

// ---------------------------------------------------------------------------
// Viterbi: one CTA per sample. Fuses pot = pf + pb.
// ---------------------------------------------------------------------------
#define VIT_SMEM (96*96*4 + 2*96*4 + 255*96 + 64)

__global__ __launch_bounds__(128)
void viterbi_kernel(float* __restrict__ potF, const float* __restrict__ potB,
                    const float* __restrict__ trans, float* __restrict__ dec)
{
    extern __shared__ float sm[];
    float* tS  = sm;
    float* al  = tS + 96 * 96;
    float* al2 = al + 96;
    unsigned char* bp = (unsigned char*)(al2 + 96);
    const int tid = threadIdx.x;
    const int b = blockIdx.x;

    for (int i = tid; i < 96 * 96; i += 128) tS[i] = trans[i];
    if (tid < 96) {
        size_t i0 = ((size_t)b * TT) * 96 + tid;
        float p0 = potF[i0] + potB[i0];
        potF[i0] = p0;
        al[tid] = p0;
    }
    __syncthreads();

    for (int t = 1; t < TT; t++) {
        if (tid < 96) {
            float best = -1e30f; int bi = 0;
#pragma unroll 4
            for (int i = 0; i < 96; i++) {
                float sc = al[i] + tS[i * 96 + tid];
                if (sc > best) { best = sc; bi = i; }
            }
            size_t idx = ((size_t)b * TT + t) * 96 + tid;
            float p = potF[idx] + potB[idx];
            potF[idx] = p;
            al2[tid] = best + p;
            bp[(t - 1) * 96 + tid] = (unsigned char)bi;
        }
        __syncthreads();
        if (tid < 96) al[tid] = al2[tid];
        __syncthreads();
    }
    if (tid == 0) {
        int bestj = 0; float bv = al[0];
        for (int j = 1; j < 96; j++) if (al[j] > bv) { bv = al[j]; bestj = j; }
        int tag = bestj;
        dec[(size_t)b * TT + TT - 1] = (float)tag;
        for (int t = TT - 2; t >= 0; t--) {
            tag = bp[t * 96 + tag];
            dec[(size_t)b * TT + t] = (float)tag;
        }
    }
}

// ---------------------------------------------------------------------------
extern "C" void kernel_launch(void* const* d_in, const int* in_sizes, int n_in,
                              void* d_out, int out_size)
{
    const float* x    = (const float*)d_in[0];
    const float* Wi1f = (const float*)d_in[1];
    const float* Wh1f = (const float*)d_in[2];
    const float* b1f  = (const float*)d_in[3];
    const float* Wi2f = (const float*)d_in[4];
    const float* Wh2f = (const float*)d_in[5];
    const float* b2f  = (const float*)d_in[6];
    const float* Wi1b = (const float*)d_in[7];
    const float* Wh1b = (const float*)d_in[8];
    const float* b1b  = (const float*)d_in[9];
    const float* Wi2b = (const float*)d_in[10];
    const float* Wh2b = (const float*)d_in[11];
    const float* b2b  = (const float*)d_in[12];
    const float* Wif  = (const float*)d_in[13];
    const float* Whf  = (const float*)d_in[14];
    const float* bf   = (const float*)d_in[15];
    const float* Wib  = (const float*)d_in[16];
    const float* Whb  = (const float*)d_in[17];
    const float* bb   = (const float*)d_in[18];
    const float* trans= (const float*)d_in[19];

    float* dec = (float*)d_out;
    float* pot = (float*)d_out + BT;

    float *xg1f, *xg1b, *xg2f, *xg2b, *h1f, *h1b, *hcat, *xgFf, *xgBf, *potB;
    cudaGetSymbolAddress((void**)&xg1f, g_xg1f);
    cudaGetSymbolAddress((void**)&xg1b, g_xg1b);
    cudaGetSymbolAddress((void**)&xg2f, g_xg2f);
    cudaGetSymbolAddress((void**)&xg2b, g_xg2b);
    cudaGetSymbolAddress((void**)&h1f,  g_h1f);
    cudaGetSymbolAddress((void**)&h1b,  g_h1b);
    cudaGetSymbolAddress((void**)&hcat, g_hcat);
    cudaGetSymbolAddress((void**)&xgFf, g_xgFf);
    cudaGetSymbolAddress((void**)&xgBf, g_xgBf);
    cudaGetSymbolAddress((void**)&potB, g_potB);

    cudaFuncSetAttribute(scan_persist_kernel,
                         cudaFuncAttributeMaxDynamicSharedMemorySize, SCAN_SMEM);
    cudaFuncSetAttribute(final_lstm_kernel,
                         cudaFuncAttributeMaxDynamicSharedMemorySize, FIN_SMEM);
    cudaFuncSetAttribute(viterbi_kernel,
                         cudaFuncAttributeMaxDynamicSharedMemorySize, VIT_SMEM);

    dim3 g1(1024 / 128, BT / 128);  // (8, 256)
    gemm_bias_kernel<<<g1, 256>>>(x, Wi1f, b1f, xg1f, BT, 1024, 512);
    gemm_bias_kernel<<<g1, 256>>>(x, Wi1b, b1b, xg1b, BT, 1024, 512);

    dim3 gs(8, 8, 2);
    scan_persist_kernel<<<gs, 256, SCAN_SMEM>>>(xg1f, xg1b, Wh1f, Wh1b,
                                                h1f, h1b, 256, 0, 0);

    gemm_bias_kernel<<<g1, 256>>>(h1f, Wi2f, b2f, xg2f, BT, 1024, 256);
    gemm_bias_kernel<<<g1, 256>>>(h1b, Wi2b, b2b, xg2b, BT, 1024, 256);

    scan_persist_kernel<<<gs, 256, SCAN_SMEM>>>(xg2f, xg2b, Wh2f, Wh2b,
                                                hcat, hcat, 512, 0, 256);

    dim3 g2(384 / 128, BT / 128);   // (3, 256)
    gemm_bias_kernel<<<g2, 256>>>(hcat, Wif, bf, xgFf, BT, 384, 512);
    gemm_bias_kernel<<<g2, 256>>>(hcat, Wib, bb, xgBf, BT, 384, 512);

    dim3 gf(BB, 2);
    final_lstm_kernel<<<gf, 384, FIN_SMEM>>>(xgFf, xgBf, Whf, Whb, pot, potB);
    viterbi_kernel<<<BB, 128, VIT_SMEM>>>(pot, potB, trans, dec);
}

// round 13
// speedup vs baseline: 1.5269x; 1.5269x over previous
#include <cuda_runtime.h>
#include <math.h>

#define BB 128
#define TT 256
#define DD 512
#define HH 256
#define NC 96
#define BT (BB*TT)

// ---------------- scratch (static device globals; no runtime alloc) --------
__device__ float g_xg1f[(size_t)BT*1024];
__device__ float g_xg1b[(size_t)BT*1024];
__device__ float g_xg2f[(size_t)BT*1024];
__device__ float g_xg2b[(size_t)BT*1024];
__device__ float g_h1f[(size_t)BT*HH];
__device__ float g_h1b[(size_t)BT*HH];
__device__ float g_hcat[(size_t)BT*2*HH];
__device__ float g_xgFf[(size_t)BT*384];
__device__ float g_xgBf[(size_t)BT*384];
__device__ float g_potB[(size_t)BT*NC];
__device__ float g_hstate[2*2*HH*BB];     // [buf][dir][u][b]
// 16 group barrier counters (16 CTAs each), padded 256B apart
__device__ unsigned g_cnt[16*64];

// ---------------------------------------------------------------------------
// GEMM v2 (unchanged): 128x128 tile, BK=16, f32x2, reg double-buffer.
// ---------------------------------------------------------------------------
__global__ __launch_bounds__(256, 2)
void gemm_bias_kernel(const float* __restrict__ A, const float* __restrict__ Bm,
                      const float* __restrict__ bias, float* __restrict__ C,
                      int M, int N, int K)
{
    __shared__ float As[16][132];
    __shared__ float Bs[16][128];

    const int tid = threadIdx.x;
    const int m0  = blockIdx.y * 128;
    const int n0  = blockIdx.x * 128;
    const int txn = tid & 15;
    const int tym = tid >> 4;

    const int arow = tid >> 2;
    const int akg  = (tid & 3) * 4;
    const int bkk = tid >> 5;
    const int bn  = (tid & 31) * 4;

    unsigned long long acc[4][8];
#pragma unroll
    for (int p = 0; p < 4; p++)
#pragma unroll
        for (int j = 0; j < 8; j++) acc[p][j] = 0ull;

    const int T = K / 16;
    float4 aR0, aR1, bR0, bR1;

    aR0 = *(const float4*)&A[(size_t)(m0 + arow) * K + akg];
    aR1 = *(const float4*)&A[(size_t)(m0 + 64 + arow) * K + akg];
    bR0 = *(const float4*)&Bm[(size_t)bkk * N + n0 + bn];
    bR1 = *(const float4*)&Bm[(size_t)(8 + bkk) * N + n0 + bn];
    {
        As[akg + 0][arow] = aR0.x; As[akg + 1][arow] = aR0.y;
        As[akg + 2][arow] = aR0.z; As[akg + 3][arow] = aR0.w;
        As[akg + 0][64 + arow] = aR1.x; As[akg + 1][64 + arow] = aR1.y;
        As[akg + 2][64 + arow] = aR1.z; As[akg + 3][64 + arow] = aR1.w;
        *(float4*)&Bs[bkk][bn] = bR0;
        *(float4*)&Bs[8 + bkk][bn] = bR1;
    }
    __syncthreads();

    for (int t = 0; t < T; t++) {
        if (t + 1 < T) {
            int k0 = (t + 1) * 16;
            aR0 = *(const float4*)&A[(size_t)(m0 + arow) * K + k0 + akg];
            aR1 = *(const float4*)&A[(size_t)(m0 + 64 + arow) * K + k0 + akg];
            bR0 = *(const float4*)&Bm[(size_t)(k0 + bkk) * N + n0 + bn];
            bR1 = *(const float4*)&Bm[(size_t)(k0 + 8 + bkk) * N + n0 + bn];
        }
#pragma unroll
        for (int kk = 0; kk < 16; kk++) {
            ulonglong2 aP0 = *(const ulonglong2*)&As[kk][tym * 8];
            ulonglong2 aP1 = *(const ulonglong2*)&As[kk][tym * 8 + 4];
            float4 b0 = *(const float4*)&Bs[kk][txn * 8];
            float4 b1 = *(const float4*)&Bs[kk][txn * 8 + 4];
            unsigned long long bd[8];
            asm("mov.b64 %0, {%1, %1};" : "=l"(bd[0]) : "f"(b0.x));
            asm("mov.b64 %0, {%1, %1};" : "=l"(bd[1]) : "f"(b0.y));
            asm("mov.b64 %0, {%1, %1};" : "=l"(bd[2]) : "f"(b0.z));
            asm("mov.b64 %0, {%1, %1};" : "=l"(bd[3]) : "f"(b0.w));
            asm("mov.b64 %0, {%1, %1};" : "=l"(bd[4]) : "f"(b1.x));
            asm("mov.b64 %0, {%1, %1};" : "=l"(bd[5]) : "f"(b1.y));
            asm("mov.b64 %0, {%1, %1};" : "=l"(bd[6]) : "f"(b1.z));
            asm("mov.b64 %0, {%1, %1};" : "=l"(bd[7]) : "f"(b1.w));
            unsigned long long ap[4] = {aP0.x, aP0.y, aP1.x, aP1.y};
#pragma unroll
            for (int p = 0; p < 4; p++)
#pragma unroll
                for (int j = 0; j < 8; j++)
                    asm("fma.rn.f32x2 %0, %1, %2, %0;"
                        : "+l"(acc[p][j]) : "l"(ap[p]), "l"(bd[j]));
        }
        __syncthreads();
        if (t + 1 < T) {
            As[akg + 0][arow] = aR0.x; As[akg + 1][arow] = aR0.y;
            As[akg + 2][arow] = aR0.z; As[akg + 3][arow] = aR0.w;
            As[akg + 0][64 + arow] = aR1.x; As[akg + 1][64 + arow] = aR1.y;
            As[akg + 2][64 + arow] = aR1.z; As[akg + 3][64 + arow] = aR1.w;
            *(float4*)&Bs[bkk][bn] = bR0;
            *(float4*)&Bs[8 + bkk][bn] = bR1;
            __syncthreads();
        }
    }

    float4 z0 = *(const float4*)&bias[n0 + txn * 8];
    float4 z1 = *(const float4*)&bias[n0 + txn * 8 + 4];
    float bz[8] = {z0.x, z0.y, z0.z, z0.w, z1.x, z1.y, z1.z, z1.w};
#pragma unroll
    for (int p = 0; p < 4; p++) {
        float lo[8], hi[8];
#pragma unroll
        for (int j = 0; j < 8; j++)
            asm("mov.b64 {%0, %1}, %2;" : "=f"(lo[j]), "=f"(hi[j]) : "l"(acc[p][j]));
        size_t r0 = (size_t)(m0 + tym * 8 + 2 * p) * N + n0 + txn * 8;
        size_t r1 = r0 + N;
        float4 v;
        v.x = lo[0] + bz[0]; v.y = lo[1] + bz[1]; v.z = lo[2] + bz[2]; v.w = lo[3] + bz[3];
        *(float4*)&C[r0] = v;
        v.x = lo[4] + bz[4]; v.y = lo[5] + bz[5]; v.z = lo[6] + bz[6]; v.w = lo[7] + bz[7];
        *(float4*)&C[r0 + 4] = v;
        v.x = hi[0] + bz[0]; v.y = hi[1] + bz[1]; v.z = hi[2] + bz[2]; v.w = hi[3] + bz[3];
        *(float4*)&C[r1] = v;
        v.x = hi[4] + bz[4]; v.y = hi[5] + bz[5]; v.z = hi[6] + bz[6]; v.w = hi[7] + bz[7];
        *(float4*)&C[r1 + 4] = v;
    }
}

// ---------------------------------------------------------------------------
__global__ void reset_bar_kernel()
{
    int i = threadIdx.x;
    if (i < 16) g_cnt[i * 64] = 0u;
}

// ---------------------------------------------------------------------------
// Persistent dual-direction LSTM scan v5: R10 algorithm, but CTAs halved to
// 16-unit slices -> grid (16,8,2) = 256 CTAs = 2 CTAs/SM. Each SM hosts one
// fwd-chain CTA and one bwd-chain CTA (contiguous CLC placement); their
// barrier waits are uncorrelated, so one chain's exchange latency is hidden
// under the other's z-compute. Barrier protocol identical (16 arrivals/group).
// ---------------------------------------------------------------------------
#define ZROW 33  // u64 per column row: 8 bpairs x 4 bands + 1 pad
#define SCAN_SMEM ((256*64 + 256*16) * 4 + 64*ZROW*8)

__global__ __launch_bounds__(256, 2)
void scan_persist_kernel(const float* __restrict__ xgF, const float* __restrict__ xgB,
                         const float* __restrict__ WhF, const float* __restrict__ WhB,
                         float* __restrict__ outF, float* __restrict__ outB,
                         int outStride, int offF, int offB)
{
    extern __shared__ float sm[];
    float* Ws = sm;                               // [256 k][64 c]
    float* hT = Ws + 256 * 64;                    // [256 k][16 b]
    unsigned long long* zP =
        (unsigned long long*)(hT + 256 * 16);     // [64 c][ZROW]

    const int tid = threadIdx.x;
    const int u0  = blockIdx.x * 16;              // 16-unit slice
    const int b0  = blockIdx.y * 16;
    const int dir = blockIdx.z;
    const float* Wh = dir ? WhB : WhF;
    const float* xg = dir ? xgB : xgF;
    float* out = dir ? outB : outF;
    const int off = dir ? offB : offF;
    unsigned* cnt = &g_cnt[(dir * 8 + blockIdx.y) * 64];

    // stage Wh slice once: Ws[k][gate*16+q] = Wh[k][gate*256+u0+q]
#pragma unroll
    for (int i = 0; i < 16; i++) {
        int v = i * 256 + tid;              // float4 index, 4096 total
        int k = v >> 4, c4v = v & 15;
        int gate = c4v >> 2, q4 = (c4v & 3) * 4;
        float4 w = *(const float4*)(Wh + (size_t)k * 1024 + gate * 256 + u0 + q4);
        *(float4*)(Ws + k * 64 + gate * 16 + q4) = w;
    }

    // z-phase mapping: 32 colg(2c) x 2 bgz(8b) x 4 bands(64k)
    const int colg = tid & 31;
    const int bgz  = (tid >> 5) & 1;
    const int band = tid >> 6;
    const int c2   = colg * 2;

    // gate-phase mapping: one unit, one batch per thread (16x16 = 256)
    const int gq = tid & 15;            // unit u0 + gq
    const int gb = tid >> 4;            // batch 0..15
    const int bg = b0 + gb;
    float creg = 0.0f;

#pragma unroll 1
    for (int s = 0; s < TT; s++) {
        const int t = dir ? (TT - 1 - s) : s;
        const float* hr = g_hstate + (size_t)(s & 1) * (2 * HH * BB) + dir * (HH * BB);
        float*       hw = g_hstate + (size_t)((s + 1) & 1) * (2 * HH * BB) + dir * (HH * BB);

        // stage h FIRST (critical path)
#pragma unroll
        for (int i = 0; i < 4; i++) {
            int v = i * 256 + tid;
            int k = v >> 2, b4 = v & 3;
            float4 h = __ldcg((const float4*)(hr + k * 128 + b0 + b4 * 4));
            *(float4*)(hT + k * 16 + b4 * 4) = h;
        }

        // prefetch xg gate inputs (coalesced scalars)
        const size_t xrow = ((size_t)bg * TT + t) * 1024;
        float xv0 = xg[xrow + 0 * 256 + u0 + gq];
        float xv1 = xg[xrow + 1 * 256 + u0 + gq];
        float xv2 = xg[xrow + 2 * 256 + u0 + gq];
        float xv3 = xg[xrow + 3 * 256 + u0 + gq];

        __syncthreads();

        // z partial: 2 cols x 4 b-pairs over this thread's 64-k band
        unsigned long long acc[2][4];
#pragma unroll
        for (int j = 0; j < 2; j++)
#pragma unroll
            for (int p = 0; p < 4; p++) acc[j][p] = 0ull;

        const float* hb = hT + bgz * 8;
        const float* wb = Ws + c2;
        const int kb = band * 64;
#pragma unroll 4
        for (int kk = 0; kk < 64; kk++) {
            int k = kb + kk;
            ulonglong2 h01 = *(const ulonglong2*)(hb + k * 16);
            ulonglong2 h23 = *(const ulonglong2*)(hb + k * 16 + 4);
            float2 w2 = *(const float2*)(wb + k * 64);
            unsigned long long wd0, wd1;
            asm("mov.b64 %0, {%1, %1};" : "=l"(wd0) : "f"(w2.x));
            asm("mov.b64 %0, {%1, %1};" : "=l"(wd1) : "f"(w2.y));
            asm("fma.rn.f32x2 %0, %1, %2, %0;" : "+l"(acc[0][0]) : "l"(h01.x), "l"(wd0));
            asm("fma.rn.f32x2 %0, %1, %2, %0;" : "+l"(acc[0][1]) : "l"(h01.y), "l"(wd0));
            asm("fma.rn.f32x2 %0, %1, %2, %0;" : "+l"(acc[0][2]) : "l"(h23.x), "l"(wd0));
            asm("fma.rn.f32x2 %0, %1, %2, %0;" : "+l"(acc[0][3]) : "l"(h23.y), "l"(wd0));
            asm("fma.rn.f32x2 %0, %1, %2, %0;" : "+l"(acc[1][0]) : "l"(h01.x), "l"(wd1));
            asm("fma.rn.f32x2 %0, %1, %2, %0;" : "+l"(acc[1][1]) : "l"(h01.y), "l"(wd1));
            asm("fma.rn.f32x2 %0, %1, %2, %0;" : "+l"(acc[1][2]) : "l"(h23.x), "l"(wd1));
            asm("fma.rn.f32x2 %0, %1, %2, %0;" : "+l"(acc[1][3]) : "l"(h23.y), "l"(wd1));
        }
#pragma unroll
        for (int j = 0; j < 2; j++)
#pragma unroll
            for (int p = 0; p < 4; p++)
                zP[(c2 + j) * ZROW + (bgz * 4 + p) * 4 + band] = acc[j][p];
        __syncthreads();

        // gate phase: thread -> unit u0+gq, batch gb
        {
            const unsigned* zw = (const unsigned*)zP;
            const int bp4 = (gb >> 1) * 4;
            const int lohi = gb & 1;
            float zz[4];
#pragma unroll
            for (int g = 0; g < 4; g++) {
                int c = g * 16 + gq;
                const unsigned* r = zw + 2 * (c * ZROW + bp4) + lohi;
                zz[g] = __uint_as_float(r[0]) + __uint_as_float(r[2])
                      + __uint_as_float(r[4]) + __uint_as_float(r[6]);
            }
            float zi = zz[0] + xv0;
            float zf = zz[1] + xv1;
            float zg = zz[2] + xv2;
            float zo = zz[3] + xv3;
            float iv = 1.f / (1.f + expf(-zi));
            float fv = 1.f / (1.f + expf(-zf));
            float ov = 1.f / (1.f + expf(-zo));
            float cn = fv * creg + iv * tanhf(zg);
            float hn = ov * tanhf(cn);
            creg = cn;
            __stcg(hw + (size_t)(u0 + gq) * BB + bg, hn);
            out[((size_t)bg * TT + t) * outStride + off + u0 + gq] = hn;
        }

        // group counting barrier: release-RMW arrive; acquire-poll same counter
        __syncthreads();
        if (tid == 0) {
            unsigned dummy;
            asm volatile("atom.add.release.gpu.global.u32 %0, [%1], 1;"
                         : "=r"(dummy) : "l"(cnt) : "memory");
            unsigned tgt = (unsigned)(s + 1) * 16u;
            unsigned f;
            do {
                asm volatile("ld.acquire.gpu.global.u32 %0, [%1];"
                             : "=r"(f) : "l"(cnt) : "memory");
            } while (f < tgt);
        }
        __syncthreads();
    }
}

// ---------------------------------------------------------------------------
// Final LSTMs (C=96, softmax activation), one CTA per (sample, direction).
// ---------------------------------------------------------------------------
__device__ __forceinline__ float blockReduce96(float v, bool isMax,
                                               volatile float* red, int tid)
{
#pragma unroll
    for (int o = 16; o > 0; o >>= 1) {
        float w = __shfl_down_sync(0xffffffffu, v, o);
        v = isMax ? fmaxf(v, w) : v + w;
    }
    if (tid < 96 && (tid & 31) == 0) red[tid >> 5] = v;
    __syncthreads();
    float r = isMax ? fmaxf(fmaxf(red[0], red[1]), red[2])
                    : red[0] + red[1] + red[2];
    __syncthreads();
    return r;
}

#define FIN_SMEM ((96*384 + 384 + 96 + 96 + 4) * 4)

__global__ __launch_bounds__(384)
void final_lstm_kernel(const float* __restrict__ xgF, const float* __restrict__ xgB,
                       const float* __restrict__ WhF, const float* __restrict__ WhB,
                       float* __restrict__ potF, float* __restrict__ potB)
{
    extern __shared__ float sm[];
    float* WhS = sm;
    float* zS  = WhS + 96 * 384;
    float* hS  = zS + 384;
    float* cS  = hS + 96;
    float* red = cS + 96;
    const int tid = threadIdx.x;
    const int b = blockIdx.x;
    const int dir = blockIdx.y;

    const float* Wh = dir ? WhB : WhF;
    const float* xg = dir ? xgB : xgF;
    float* pot = dir ? potB : potF;

    for (int i = tid; i < 96 * 384; i += 384) WhS[i] = Wh[i];
    if (tid < 96) { hS[tid] = 0.f; cS[tid] = 0.f; }
    __syncthreads();

    for (int s = 0; s < TT; s++) {
        int t = dir ? (TT - 1 - s) : s;
        float a = xg[((size_t)b * TT + t) * 384 + tid];
#pragma unroll 4
        for (int k = 0; k < 96; k++) a += hS[k] * WhS[k * 384 + tid];
        zS[tid] = a;
        __syncthreads();

        bool v = tid < 96;
        float gv = v ? zS[192 + tid] : -1e30f;
        float gmax = blockReduce96(gv, true, red, tid);
        float ge = v ? expf(gv - gmax) : 0.f;
        float gsum = blockReduce96(ge, false, red, tid);
        float cn = 0.f;
        if (v) {
            float iv = 1.f / (1.f + expf(-zS[tid]));
            float fv = 1.f / (1.f + expf(-zS[96 + tid]));
            cn = fv * cS[tid] + iv * (ge / gsum);
        }
        float cmax = blockReduce96(v ? cn : -1e30f, true, red, tid);
        float ce = v ? expf(cn - cmax) : 0.f;
        float csum = blockReduce96(ce, false, red, tid);
        if (v) {
            float ov = 1.f / (1.f + expf(-zS[288 + tid]));
            float hv = ov * (ce / csum);
            cS[tid] = cn;
            hS[tid] = hv;
            pot[((size_t)b * TT + t) * 96 + tid] = hv;
        }
        __syncthreads();
    }
}

// ---------------------------------------------------------------------------
// Viterbi: one CTA per sample. Fuses pot = pf + pb.
// ---------------------------------------------------------------------------
#define VIT_SMEM (96*96*4 + 2*96*4 + 255*96 + 64)

__global__ __launch_bounds__(128)
void viterbi_kernel(float* __restrict__ potF, const float* __restrict__ potB,
                    const float* __restrict__ trans, float* __restrict__ dec)
{
    extern __shared__ float sm[];
    float* tS  = sm;
    float* al  = tS + 96 * 96;
    float* al2 = al + 96;
    unsigned char* bp = (unsigned char*)(al2 + 96);
    const int tid = threadIdx.x;
    const int b = blockIdx.x;

    for (int i = tid; i < 96 * 96; i += 128) tS[i] = trans[i];
    if (tid < 96) {
        size_t i0 = ((size_t)b * TT) * 96 + tid;
        float p0 = potF[i0] + potB[i0];
        potF[i0] = p0;
        al[tid] = p0;
    }
    __syncthreads();

    for (int t = 1; t < TT; t++) {
        if (tid < 96) {
            float best = -1e30f; int bi = 0;
#pragma unroll 4
            for (int i = 0; i < 96; i++) {
                float sc = al[i] + tS[i * 96 + tid];
                if (sc > best) { best = sc; bi = i; }
            }
            size_t idx = ((size_t)b * TT + t) * 96 + tid;
            float p = potF[idx] + potB[idx];
            potF[idx] = p;
            al2[tid] = best + p;
            bp[(t - 1) * 96 + tid] = (unsigned char)bi;
        }
        __syncthreads();
        if (tid < 96) al[tid] = al2[tid];
        __syncthreads();
    }
    if (tid == 0) {
        int bestj = 0; float bv = al[0];
        for (int j = 1; j < 96; j++) if (al[j] > bv) { bv = al[j]; bestj = j; }
        int tag = bestj;
        dec[(size_t)b * TT + TT - 1] = (float)tag;
        for (int t = TT - 2; t >= 0; t--) {
            tag = bp[t * 96 + tag];
            dec[(size_t)b * TT + t] = (float)tag;
        }
    }
}

// ---------------------------------------------------------------------------
extern "C" void kernel_launch(void* const* d_in, const int* in_sizes, int n_in,
                              void* d_out, int out_size)
{
    const float* x    = (const float*)d_in[0];
    const float* Wi1f = (const float*)d_in[1];
    const float* Wh1f = (const float*)d_in[2];
    const float* b1f  = (const float*)d_in[3];
    const float* Wi2f = (const float*)d_in[4];
    const float* Wh2f = (const float*)d_in[5];
    const float* b2f  = (const float*)d_in[6];
    const float* Wi1b = (const float*)d_in[7];
    const float* Wh1b = (const float*)d_in[8];
    const float* b1b  = (const float*)d_in[9];
    const float* Wi2b = (const float*)d_in[10];
    const float* Wh2b = (const float*)d_in[11];
    const float* b2b  = (const float*)d_in[12];
    const float* Wif  = (const float*)d_in[13];
    const float* Whf  = (const float*)d_in[14];
    const float* bf   = (const float*)d_in[15];
    const float* Wib  = (const float*)d_in[16];
    const float* Whb  = (const float*)d_in[17];
    const float* bb   = (const float*)d_in[18];
    const float* trans= (const float*)d_in[19];

    float* dec = (float*)d_out;
    float* pot = (float*)d_out + BT;

    float *xg1f, *xg1b, *xg2f, *xg2b, *h1f, *h1b, *hcat, *xgFf, *xgBf, *potB, *hst;
    cudaGetSymbolAddress((void**)&xg1f, g_xg1f);
    cudaGetSymbolAddress((void**)&xg1b, g_xg1b);
    cudaGetSymbolAddress((void**)&xg2f, g_xg2f);
    cudaGetSymbolAddress((void**)&xg2b, g_xg2b);
    cudaGetSymbolAddress((void**)&h1f,  g_h1f);
    cudaGetSymbolAddress((void**)&h1b,  g_h1b);
    cudaGetSymbolAddress((void**)&hcat, g_hcat);
    cudaGetSymbolAddress((void**)&xgFf, g_xgFf);
    cudaGetSymbolAddress((void**)&xgBf, g_xgBf);
    cudaGetSymbolAddress((void**)&potB, g_potB);
    cudaGetSymbolAddress((void**)&hst,  g_hstate);

    cudaFuncSetAttribute(scan_persist_kernel,
                         cudaFuncAttributeMaxDynamicSharedMemorySize, SCAN_SMEM);
    cudaFuncSetAttribute(final_lstm_kernel,
                         cudaFuncAttributeMaxDynamicSharedMemorySize, FIN_SMEM);
    cudaFuncSetAttribute(viterbi_kernel,
                         cudaFuncAttributeMaxDynamicSharedMemorySize, VIT_SMEM);

    dim3 g1(1024 / 128, BT / 128);  // (8, 256)
    gemm_bias_kernel<<<g1, 256>>>(x, Wi1f, b1f, xg1f, BT, 1024, 512);
    gemm_bias_kernel<<<g1, 256>>>(x, Wi1b, b1b, xg1b, BT, 1024, 512);

    dim3 gs(16, 8, 2);   // 256 CTAs, 2 per SM
    cudaMemsetAsync(hst, 0, sizeof(float) * 2 * 2 * HH * BB);
    reset_bar_kernel<<<1, 32>>>();
    scan_persist_kernel<<<gs, 256, SCAN_SMEM>>>(xg1f, xg1b, Wh1f, Wh1b,
                                                h1f, h1b, 256, 0, 0);

    gemm_bias_kernel<<<g1, 256>>>(h1f, Wi2f, b2f, xg2f, BT, 1024, 256);
    gemm_bias_kernel<<<g1, 256>>>(h1b, Wi2b, b2b, xg2b, BT, 1024, 256);

    cudaMemsetAsync(hst, 0, sizeof(float) * 2 * 2 * HH * BB);
    reset_bar_kernel<<<1, 32>>>();
    scan_persist_kernel<<<gs, 256, SCAN_SMEM>>>(xg2f, xg2b, Wh2f, Wh2b,
                                                hcat, hcat, 512, 0, 256);

    dim3 g2(384 / 128, BT / 128);   // (3, 256)
    gemm_bias_kernel<<<g2, 256>>>(hcat, Wif, bf, xgFf, BT, 384, 512);
    gemm_bias_kernel<<<g2, 256>>>(hcat, Wib, bb, xgBf, BT, 384, 512);

    dim3 gf(BB, 2);
    final_lstm_kernel<<<gf, 384, FIN_SMEM>>>(xgFf, xgBf, Whf, Whb, pot, potB);
    viterbi_kernel<<<BB, 128, VIT_SMEM>>>(pot, potB, trans, dec);
}